// round 1
// baseline (speedup 1.0000x reference)
#include <cuda_runtime.h>
#include <math.h>

#define J 23

// Scratch: A matrices (first 3 rows of each 4x4, as 3 float4 per joint) + constants.
static __device__ float4 g_A[J * 3];
static __device__ float  g_const[4];   // c, ox, oy, oz

__device__ __forceinline__ void mat4mul(const float* a, const float* b, float* c) {
    #pragma unroll
    for (int r = 0; r < 4; r++)
        #pragma unroll
        for (int col = 0; col < 4; col++) {
            float s = 0.f;
            #pragma unroll
            for (int k = 0; k < 4; k++) s += a[r * 4 + k] * b[k * 4 + col];
            c[r * 4 + col] = s;
        }
}

// Single-thread prep: pose -> rodrigues -> FK chain -> A, small outputs.
__global__ void prep_kernel(const float* __restrict__ jr,      // joints_rest [J,3]
                            const float* __restrict__ p0, const float* __restrict__ p1,
                            const float* __restrict__ p2, const float* __restrict__ p3,
                            const float* __restrict__ p4, const float* __restrict__ p5,
                            const float* __restrict__ p12, const float* __restrict__ p13,
                            const float* __restrict__ disp,    // [3]
                            const float* __restrict__ scale,   // [1]
                            const float* __restrict__ loc,     // [3]
                            float* __restrict__ out,
                            int B, int V)
{
    if (threadIdx.x != 0 || blockIdx.x != 0) return;

    const int PAR[J] = {-1,0,1,1,3,4,5,4,7,4,9,1,11,12,13,12,15,12,17,0,19,0,21};
    const float PI = 3.14159265358979323846f;

    float pose[J][3];
    #pragma unroll
    for (int j = 0; j < J; j++) { pose[j][0] = 0.f; pose[j][1] = 0.f; pose[j][2] = 0.f; }

    #pragma unroll
    for (int k = 0; k < 3; k++) {
        pose[0][k]  = (PI / 2.f) * tanhf(p0[k]);
        pose[1][k]  = (PI / 4.f) * tanhf(p1[k]);
        pose[2][k]  = (PI / 9.f) * tanhf(p2[k]);
        pose[3][k]  = (PI / 3.f) * tanhf(p3[k]);
        pose[4][k]  = (PI / 3.f) * tanhf(p4[k]);
        pose[5][k]  = (PI / 3.f) * tanhf(p5[k]);
        pose[12][k] = (PI / 3.f) * tanhf(p12[k]);
        pose[13][k] = (PI / 3.f) * tanhf(p13[k]);
    }
    pose[11][0] =  (PI / 3.f) * tanhf(p3[0]);
    pose[11][1] = -(PI / 3.f) * tanhf(p3[1]);
    pose[11][2] = -(PI / 3.f) * tanhf(p3[2]);

    // Rodrigues per joint -> local transforms
    float Tl[J][16];
    #pragma unroll
    for (int j = 0; j < J; j++) {
        float rx = pose[j][0], ry = pose[j][1], rz = pose[j][2];
        float ang = sqrtf(rx * rx + ry * ry + rz * rz + 1e-12f);
        float inv = 1.f / ang;
        float x = rx * inv, y = ry * inv, z = rz * inv;
        float s = sinf(ang), c = cosf(ang), t = 1.f - c;
        // R = I + s*K + (1-c)*K^2
        float R[9];
        R[0] = 1.f + t * (-(z * z) - (y * y));
        R[1] = -s * z + t * (x * y);
        R[2] =  s * y + t * (x * z);
        R[3] =  s * z + t * (x * y);
        R[4] = 1.f + t * (-(z * z) - (x * x));
        R[5] = -s * x + t * (y * z);
        R[6] = -s * y + t * (x * z);
        R[7] =  s * x + t * (y * z);
        R[8] = 1.f + t * (-(y * y) - (x * x));

        float relx, rely, relz;
        if (PAR[j] < 0) { relx = jr[3*j]; rely = jr[3*j+1]; relz = jr[3*j+2]; }
        else {
            relx = jr[3*j]   - jr[3*PAR[j]];
            rely = jr[3*j+1] - jr[3*PAR[j]+1];
            relz = jr[3*j+2] - jr[3*PAR[j]+2];
        }
        Tl[j][0]=R[0]; Tl[j][1]=R[1]; Tl[j][2]=R[2];  Tl[j][3]=relx;
        Tl[j][4]=R[3]; Tl[j][5]=R[4]; Tl[j][6]=R[5];  Tl[j][7]=rely;
        Tl[j][8]=R[6]; Tl[j][9]=R[7]; Tl[j][10]=R[8]; Tl[j][11]=relz;
        Tl[j][12]=0.f; Tl[j][13]=0.f; Tl[j][14]=0.f;  Tl[j][15]=1.f;
    }

    // FK chain
    float G[J][16];
    #pragma unroll
    for (int k = 0; k < 16; k++) G[0][k] = Tl[0][k];
    for (int j = 1; j < J; j++) mat4mul(G[PAR[j]], Tl[j], G[j]);

    float cst = 0.0035f * scale[0];
    float ox = loc[0] + 0.1f * tanhf(disp[0]);
    float oy = loc[1] + 0.1f * tanhf(disp[1]);
    float oz = loc[2] + 0.1f * tanhf(disp[2]);
    g_const[0] = cst; g_const[1] = ox; g_const[2] = oy; g_const[3] = oz;

    // A = G with translation corrected; store rows 0..2 as float4s
    float* gA = (float*)g_A;
    for (int j = 0; j < J; j++) {
        float jx = jr[3*j], jy = jr[3*j+1], jz = jr[3*j+2];
        float tcx = G[j][0]*jx + G[j][1]*jy + G[j][2]*jz;
        float tcy = G[j][4]*jx + G[j][5]*jy + G[j][6]*jz;
        float tcz = G[j][8]*jx + G[j][9]*jy + G[j][10]*jz;
        gA[j*12+0]=G[j][0]; gA[j*12+1]=G[j][1]; gA[j*12+2]=G[j][2];  gA[j*12+3]=G[j][3]-tcx;
        gA[j*12+4]=G[j][4]; gA[j*12+5]=G[j][5]; gA[j*12+6]=G[j][6];  gA[j*12+7]=G[j][7]-tcy;
        gA[j*12+8]=G[j][8]; gA[j*12+9]=G[j][9]; gA[j*12+10]=G[j][10];gA[j*12+11]=G[j][11]-tcz;
    }

    // Small outputs: pose, joints_out, scale, displacement
    long base = (long)B * 3L * (long)V;
    for (int j = 0; j < J; j++) {
        out[base + 3*j + 0] = pose[j][0];
        out[base + 3*j + 1] = pose[j][1];
        out[base + 3*j + 2] = pose[j][2];
        // posed joints = G translation
        float px = G[j][3], py = G[j][7], pz = G[j][11];
        out[base + 69 + 3*j + 0] = cst * px + ox;
        out[base + 69 + 3*j + 1] = cst * py + oy;
        out[base + 69 + 3*j + 2] = cst * pz + oz;
    }
    out[base + 138] = scale[0];
    out[base + 139] = disp[0];
    out[base + 140] = disp[1];
    out[base + 141] = disp[2];
}

// Per-vertex LBS: T = sum_j w_j * A_j ; y = T @ [v,1]; write B broadcast copies
// plus the local_adjust passthrough.
__global__ void __launch_bounds__(256) lbs_kernel(
    const float* __restrict__ vt,   // v_template [V,3]
    const float* __restrict__ sk,   // skinning   [V,23]
    const float* __restrict__ la,   // local_adjust [V,3]
    float* __restrict__ out,
    int V, int B)
{
    __shared__ float4 sA[J * 3];
    __shared__ float  sc[4];
    int tid = threadIdx.x;
    if (tid < J * 3) sA[tid] = g_A[tid];
    if (tid < 4)     sc[tid] = g_const[tid];
    __syncthreads();

    int v = blockIdx.x * blockDim.x + tid;
    if (v >= V) return;

    long b3 = 3L * (long)v;
    float la0 = la[b3 + 0], la1 = la[b3 + 1], la2 = la[b3 + 2];
    float vx = vt[b3 + 0] + 0.1f * tanhf(la0);
    float vy = vt[b3 + 1] + 0.1f * tanhf(la1);
    float vz = vt[b3 + 2] + 0.1f * tanhf(la2);

    const float* skv = sk + 23L * (long)v;

    float4 t0 = make_float4(0.f, 0.f, 0.f, 0.f);
    float4 t1 = make_float4(0.f, 0.f, 0.f, 0.f);
    float4 t2 = make_float4(0.f, 0.f, 0.f, 0.f);

    #pragma unroll
    for (int j = 0; j < J; j++) {
        float w = __ldg(skv + j);
        float4 a0 = sA[3*j + 0];
        float4 a1 = sA[3*j + 1];
        float4 a2 = sA[3*j + 2];
        t0.x = fmaf(w, a0.x, t0.x); t0.y = fmaf(w, a0.y, t0.y);
        t0.z = fmaf(w, a0.z, t0.z); t0.w = fmaf(w, a0.w, t0.w);
        t1.x = fmaf(w, a1.x, t1.x); t1.y = fmaf(w, a1.y, t1.y);
        t1.z = fmaf(w, a1.z, t1.z); t1.w = fmaf(w, a1.w, t1.w);
        t2.x = fmaf(w, a2.x, t2.x); t2.y = fmaf(w, a2.y, t2.y);
        t2.z = fmaf(w, a2.z, t2.z); t2.w = fmaf(w, a2.w, t2.w);
    }

    float x = fmaf(t0.x, vx, fmaf(t0.y, vy, fmaf(t0.z, vz, t0.w)));
    float y = fmaf(t1.x, vx, fmaf(t1.y, vy, fmaf(t1.z, vz, t1.w)));
    float z = fmaf(t2.x, vx, fmaf(t2.y, vy, fmaf(t2.z, vz, t2.w)));

    float c  = sc[0];
    float rx = fmaf(c, x, sc[1]);
    float ry = fmaf(c, y, sc[2]);
    float rz = fmaf(c, z, sc[3]);

    long V3 = 3L * (long)V;
    #pragma unroll 4
    for (int b = 0; b < B; b++) {
        out[(long)b * V3 + b3 + 0] = rx;
        out[(long)b * V3 + b3 + 1] = ry;
        out[(long)b * V3 + b3 + 2] = rz;
    }

    // local_adjust passthrough
    long offLa = (long)B * V3 + 69 + 69 + 1 + 3;
    out[offLa + b3 + 0] = la0;
    out[offLa + b3 + 1] = la1;
    out[offLa + b3 + 2] = la2;
}

extern "C" void kernel_launch(void* const* d_in, const int* in_sizes, int n_in,
                              void* d_out, int out_size)
{
    const float* vt    = (const float*)d_in[0];
    const float* sk    = (const float*)d_in[1];
    const float* jr    = (const float*)d_in[2];
    const float* p0    = (const float*)d_in[3];
    const float* p1    = (const float*)d_in[4];
    const float* p2    = (const float*)d_in[5];
    const float* p3    = (const float*)d_in[6];
    const float* p4    = (const float*)d_in[7];
    const float* p5    = (const float*)d_in[8];
    const float* p12   = (const float*)d_in[9];
    const float* p13   = (const float*)d_in[10];
    const float* disp  = (const float*)d_in[12];
    const float* scale = (const float*)d_in[13];
    const float* loc   = (const float*)d_in[14];
    float* out = (float*)d_out;

    int V = in_sizes[0] / 3;
    long fixed = 69L + 69L + 1L + 3L + 3L * (long)V;   // pose+joints+scale+disp+local_adjust
    int B = (int)(((long)out_size - fixed) / (3L * (long)V));

    prep_kernel<<<1, 1>>>(jr, p0, p1, p2, p3, p4, p5, p12, p13,
                          disp, scale, loc, out, B, V);

    int threads = 256;
    int blocks = (V + threads - 1) / threads;
    lbs_kernel<<<blocks, threads>>>(vt, sk, (const float*)d_in[11], out, V, B);
}

// round 2
// speedup vs baseline: 1.0037x; 1.0037x over previous
#include <cuda_runtime.h>
#include <math.h>

#define J   23
#define TPB 256
#define VPB 256
#define PI_F 3.14159265358979323846f

__constant__ int cPAR[J] = {-1,0,1,1,3,4,5,4,7,4,9,1,11,12,13,12,15,12,17,0,19,0,21};

__global__ void __launch_bounds__(TPB) fused_lbs_kernel(
    const float* __restrict__ vt,    // v_template [V,3]
    const float* __restrict__ sk,    // skinning   [V,23]
    const float* __restrict__ la,    // local_adjust [V,3]
    const float* __restrict__ jr,    // joints_rest [J,3]
    const float* __restrict__ p0, const float* __restrict__ p1,
    const float* __restrict__ p2, const float* __restrict__ p3,
    const float* __restrict__ p4, const float* __restrict__ p5,
    const float* __restrict__ p12, const float* __restrict__ p13,
    const float* __restrict__ disp, const float* __restrict__ scale,
    const float* __restrict__ loc,
    float* __restrict__ out, int V, int B)
{
    __shared__ float  s_sk[VPB * 23];
    __shared__ float  s_vt[VPB * 3];
    __shared__ float  s_la[VPB * 3];
    __shared__ float  s_res[VPB * 3];
    __shared__ float4 s_A4[J * 3];
    __shared__ float  s_Tl[J * 12];
    __shared__ float  s_G[J * 12];
    __shared__ float  s_pose[J * 3];
    __shared__ float  s_c[4];

    const int tid = threadIdx.x;
    const int blk = blockIdx.x;
    const long v0 = (long)blk * VPB;
    const int nv  = (V - (int)v0 < VPB) ? (V - (int)v0) : VPB;  // 256 or 64 (both %4==0)
    const long V3 = 3L * (long)V;

    // ---- Phase 1: cooperative vectorized tile loads (in flight during FK) ----
    {
        const float4* g4 = (const float4*)(sk + v0 * 23);
        const int nS = (nv * 23) >> 2;
        #pragma unroll 2
        for (int i = tid; i < nS; i += TPB) ((float4*)s_sk)[i] = g4[i];

        const float4* gv = (const float4*)(vt + v0 * 3);
        const float4* gl = (const float4*)(la + v0 * 3);
        const int n3 = (nv * 3) >> 2;
        for (int i = tid; i < n3; i += TPB) {
            ((float4*)s_vt)[i] = gv[i];
            ((float4*)s_la)[i] = gl[i];
        }
    }

    // ---- Phase 2: warp 0 computes pose -> Rodrigues -> FK -> A (redundant per block) ----
    if (tid < 32) {
        if (tid == 31) {
            float cst = 0.0035f * scale[0];
            s_c[0] = cst;
            s_c[1] = loc[0] + 0.1f * tanhf(disp[0]);
            s_c[2] = loc[1] + 0.1f * tanhf(disp[1]);
            s_c[3] = loc[2] + 0.1f * tanhf(disp[2]);
        }
        if (tid < J) {
            // pose for this joint
            float fac = 0.f, sy = 1.f, sz = 1.f;
            const float* pp = p0;
            bool has = true;
            switch (tid) {
                case 0:  fac = PI_F / 2.f; pp = p0;  break;
                case 1:  fac = PI_F / 4.f; pp = p1;  break;
                case 2:  fac = PI_F / 9.f; pp = p2;  break;
                case 3:  fac = PI_F / 3.f; pp = p3;  break;
                case 4:  fac = PI_F / 3.f; pp = p4;  break;
                case 5:  fac = PI_F / 3.f; pp = p5;  break;
                case 11: fac = PI_F / 3.f; pp = p3;  sy = -1.f; sz = -1.f; break;
                case 12: fac = PI_F / 3.f; pp = p12; break;
                case 13: fac = PI_F / 3.f; pp = p13; break;
                default: has = false;
            }
            float px = 0.f, py = 0.f, pz = 0.f;
            if (has) {
                px = fac * tanhf(pp[0]);
                py = sy * fac * tanhf(pp[1]);
                pz = sz * fac * tanhf(pp[2]);
            }
            s_pose[3 * tid + 0] = px;
            s_pose[3 * tid + 1] = py;
            s_pose[3 * tid + 2] = pz;

            // Rodrigues
            float ang = sqrtf(px * px + py * py + pz * pz + 1e-12f);
            float inv = 1.f / ang;
            float x = px * inv, y = py * inv, z = pz * inv;
            float s = sinf(ang), c = cosf(ang), t = 1.f - c;
            float* T = &s_Tl[tid * 12];
            T[0] = 1.f + t * (-(z * z) - (y * y));
            T[1] = -s * z + t * (x * y);
            T[2] =  s * y + t * (x * z);
            T[4] =  s * z + t * (x * y);
            T[5] = 1.f + t * (-(z * z) - (x * x));
            T[6] = -s * x + t * (y * z);
            T[8] = -s * y + t * (x * z);
            T[9] =  s * x + t * (y * z);
            T[10] = 1.f + t * (-(y * y) - (x * x));

            int par = cPAR[tid];
            float jx = jr[3 * tid], jy = jr[3 * tid + 1], jz = jr[3 * tid + 2];
            if (par >= 0) { jx -= jr[3 * par]; jy -= jr[3 * par + 1]; jz -= jr[3 * par + 2]; }
            T[3] = jx; T[7] = jy; T[11] = jz;
        }
        __syncwarp();

        // FK chain: G[0] = Tl[0]; G[j] = G[par] * Tl[j] (affine compose), 12 lanes
        if (tid < 12) s_G[tid] = s_Tl[tid];
        __syncwarp();
        #pragma unroll
        for (int j = 1; j < J; j++) {
            const int p = cPAR[j];
            if (tid < 12) {
                const int r = tid >> 2, c = tid & 3;
                const float* gp = &s_G[p * 12 + r * 4];
                const float* tl = &s_Tl[j * 12];
                float v = gp[0] * tl[0 * 4 + c]
                        + gp[1] * tl[1 * 4 + c]
                        + gp[2] * tl[2 * 4 + c];
                if (c == 3) v += gp[3];
                s_G[j * 12 + tid] = v;
            }
            __syncwarp();
        }

        // A: correct translation, pack as float4 rows
        if (tid < J) {
            const float* g = &s_G[tid * 12];
            float jx = jr[3 * tid], jy = jr[3 * tid + 1], jz = jr[3 * tid + 2];
            float tcx = g[0] * jx + g[1] * jy + g[2] * jz;
            float tcy = g[4] * jx + g[5] * jy + g[6] * jz;
            float tcz = g[8] * jx + g[9] * jy + g[10] * jz;
            s_A4[tid * 3 + 0] = make_float4(g[0], g[1], g[2],  g[3]  - tcx);
            s_A4[tid * 3 + 1] = make_float4(g[4], g[5], g[6],  g[7]  - tcy);
            s_A4[tid * 3 + 2] = make_float4(g[8], g[9], g[10], g[11] - tcz);
        }
        __syncwarp();

        // Block 0: small outputs (pose, joints_out, scale, displacement)
        if (blk == 0) {
            const long base = (long)B * V3;
            if (tid < J) {
                out[base + 3 * tid + 0] = s_pose[3 * tid + 0];
                out[base + 3 * tid + 1] = s_pose[3 * tid + 1];
                out[base + 3 * tid + 2] = s_pose[3 * tid + 2];
                float cst = s_c[0];
                out[base + 69 + 3 * tid + 0] = fmaf(cst, s_G[tid * 12 + 3],  s_c[1]);
                out[base + 69 + 3 * tid + 1] = fmaf(cst, s_G[tid * 12 + 7],  s_c[2]);
                out[base + 69 + 3 * tid + 2] = fmaf(cst, s_G[tid * 12 + 11], s_c[3]);
            }
            if (tid == 31) {
                out[base + 138] = scale[0];
                out[base + 139] = disp[0];
                out[base + 140] = disp[1];
                out[base + 141] = disp[2];
            }
        }
    }
    __syncthreads();

    // ---- Phase 3: per-vertex LBS from smem ----
    if (tid < nv) {
        float la0 = s_la[3 * tid + 0], la1 = s_la[3 * tid + 1], la2 = s_la[3 * tid + 2];
        float vx = s_vt[3 * tid + 0] + 0.1f * tanhf(la0);
        float vy = s_vt[3 * tid + 1] + 0.1f * tanhf(la1);
        float vz = s_vt[3 * tid + 2] + 0.1f * tanhf(la2);

        float4 t0 = make_float4(0.f, 0.f, 0.f, 0.f);
        float4 t1 = make_float4(0.f, 0.f, 0.f, 0.f);
        float4 t2 = make_float4(0.f, 0.f, 0.f, 0.f);

        const float* skv = &s_sk[tid * 23];
        #pragma unroll
        for (int j = 0; j < J; j++) {
            float w = skv[j];
            float4 a0 = s_A4[3 * j + 0];
            float4 a1 = s_A4[3 * j + 1];
            float4 a2 = s_A4[3 * j + 2];
            t0.x = fmaf(w, a0.x, t0.x); t0.y = fmaf(w, a0.y, t0.y);
            t0.z = fmaf(w, a0.z, t0.z); t0.w = fmaf(w, a0.w, t0.w);
            t1.x = fmaf(w, a1.x, t1.x); t1.y = fmaf(w, a1.y, t1.y);
            t1.z = fmaf(w, a1.z, t1.z); t1.w = fmaf(w, a1.w, t1.w);
            t2.x = fmaf(w, a2.x, t2.x); t2.y = fmaf(w, a2.y, t2.y);
            t2.z = fmaf(w, a2.z, t2.z); t2.w = fmaf(w, a2.w, t2.w);
        }

        float x = fmaf(t0.x, vx, fmaf(t0.y, vy, fmaf(t0.z, vz, t0.w)));
        float y = fmaf(t1.x, vx, fmaf(t1.y, vy, fmaf(t1.z, vz, t1.w)));
        float z = fmaf(t2.x, vx, fmaf(t2.y, vy, fmaf(t2.z, vz, t2.w)));

        float c = s_c[0];
        s_res[3 * tid + 0] = fmaf(c, x, s_c[1]);
        s_res[3 * tid + 1] = fmaf(c, y, s_c[2]);
        s_res[3 * tid + 2] = fmaf(c, z, s_c[3]);
    }
    __syncthreads();

    // ---- Phase 4: cooperative vectorized stores ----
    {
        const int n3 = (nv * 3) >> 2;
        const float4* r4 = (const float4*)s_res;
        for (int b = 0; b < B; b++) {
            float4* go = (float4*)(out + (long)b * V3 + v0 * 3);
            for (int i = tid; i < n3; i += TPB) go[i] = r4[i];
        }
        // local_adjust passthrough (offset ≡ 2 mod 4 → float2)
        const long offLa = (long)B * V3 + 142;
        float2* gl2 = (float2*)(out + offLa + v0 * 3);
        const float2* l2 = (const float2*)s_la;
        const int n2 = (nv * 3) >> 1;
        for (int i = tid; i < n2; i += TPB) gl2[i] = l2[i];
    }
}

extern "C" void kernel_launch(void* const* d_in, const int* in_sizes, int n_in,
                              void* d_out, int out_size)
{
    const float* vt    = (const float*)d_in[0];
    const float* sk    = (const float*)d_in[1];
    const float* jr    = (const float*)d_in[2];
    const float* p0    = (const float*)d_in[3];
    const float* p1    = (const float*)d_in[4];
    const float* p2    = (const float*)d_in[5];
    const float* p3    = (const float*)d_in[6];
    const float* p4    = (const float*)d_in[7];
    const float* p5    = (const float*)d_in[8];
    const float* p12   = (const float*)d_in[9];
    const float* p13   = (const float*)d_in[10];
    const float* la    = (const float*)d_in[11];
    const float* disp  = (const float*)d_in[12];
    const float* scale = (const float*)d_in[13];
    const float* loc   = (const float*)d_in[14];
    float* out = (float*)d_out;

    int V = in_sizes[0] / 3;
    long fixed = 69L + 69L + 1L + 3L + 3L * (long)V;
    int B = (int)(((long)out_size - fixed) / (3L * (long)V));

    int blocks = (V + VPB - 1) / VPB;
    fused_lbs_kernel<<<blocks, TPB>>>(vt, sk, la, jr,
                                      p0, p1, p2, p3, p4, p5, p12, p13,
                                      disp, scale, loc, out, V, B);
}

// round 3
// speedup vs baseline: 1.2053x; 1.2008x over previous
#include <cuda_runtime.h>
#include <math.h>

#define J   23
#define TPB 256
#define VPB 256
#define PI_F 3.14159265358979323846f

__constant__ int cPAR[J] = {-1,0,1,1,3,4,5,4,7,4,9,1,11,12,13,12,15,12,17,0,19,0,21};

static __device__ float4 g_A[J * 3];
static __device__ float  g_const[4];

// ---------------- Prep: one block, 32 threads. pose -> Rodrigues -> FK -> A ----------------
__global__ void __launch_bounds__(32) prep_kernel(
    const float* __restrict__ jr,
    const float* __restrict__ p0, const float* __restrict__ p1,
    const float* __restrict__ p2, const float* __restrict__ p3,
    const float* __restrict__ p4, const float* __restrict__ p5,
    const float* __restrict__ p12, const float* __restrict__ p13,
    const float* __restrict__ disp, const float* __restrict__ scale,
    const float* __restrict__ loc,
    float* __restrict__ out, int B, int V)
{
    __shared__ float s_Tl[J * 12];
    __shared__ float s_G[J * 12];
    __shared__ float s_pose[J * 3];

    const int tid = threadIdx.x;

    float cst = 0.f, ox = 0.f, oy = 0.f, oz = 0.f;
    if (tid == 31) {
        cst = 0.0035f * scale[0];
        ox = loc[0] + 0.1f * tanhf(disp[0]);
        oy = loc[1] + 0.1f * tanhf(disp[1]);
        oz = loc[2] + 0.1f * tanhf(disp[2]);
        g_const[0] = cst; g_const[1] = ox; g_const[2] = oy; g_const[3] = oz;
    }

    if (tid < J) {
        float fac = 0.f, sy = 1.f, sz = 1.f;
        const float* pp = p0;
        bool has = true;
        switch (tid) {
            case 0:  fac = PI_F / 2.f; pp = p0;  break;
            case 1:  fac = PI_F / 4.f; pp = p1;  break;
            case 2:  fac = PI_F / 9.f; pp = p2;  break;
            case 3:  fac = PI_F / 3.f; pp = p3;  break;
            case 4:  fac = PI_F / 3.f; pp = p4;  break;
            case 5:  fac = PI_F / 3.f; pp = p5;  break;
            case 11: fac = PI_F / 3.f; pp = p3;  sy = -1.f; sz = -1.f; break;
            case 12: fac = PI_F / 3.f; pp = p12; break;
            case 13: fac = PI_F / 3.f; pp = p13; break;
            default: has = false;
        }
        float px = 0.f, py = 0.f, pz = 0.f;
        if (has) {
            px = fac * tanhf(pp[0]);
            py = sy * fac * tanhf(pp[1]);
            pz = sz * fac * tanhf(pp[2]);
        }
        s_pose[3 * tid + 0] = px;
        s_pose[3 * tid + 1] = py;
        s_pose[3 * tid + 2] = pz;

        float ang = sqrtf(px * px + py * py + pz * pz + 1e-12f);
        float inv = 1.f / ang;
        float x = px * inv, y = py * inv, z = pz * inv;
        float s = sinf(ang), c = cosf(ang), t = 1.f - c;
        float* T = &s_Tl[tid * 12];
        T[0] = 1.f + t * (-(z * z) - (y * y));
        T[1] = -s * z + t * (x * y);
        T[2] =  s * y + t * (x * z);
        T[4] =  s * z + t * (x * y);
        T[5] = 1.f + t * (-(z * z) - (x * x));
        T[6] = -s * x + t * (y * z);
        T[8] = -s * y + t * (x * z);
        T[9] =  s * x + t * (y * z);
        T[10] = 1.f + t * (-(y * y) - (x * x));

        int par = cPAR[tid];
        float jx = jr[3 * tid], jy = jr[3 * tid + 1], jz = jr[3 * tid + 2];
        if (par >= 0) { jx -= jr[3 * par]; jy -= jr[3 * par + 1]; jz -= jr[3 * par + 2]; }
        T[3] = jx; T[7] = jy; T[11] = jz;
    }
    __syncwarp();

    if (tid < 12) s_G[tid] = s_Tl[tid];
    __syncwarp();
    #pragma unroll
    for (int j = 1; j < J; j++) {
        const int p = cPAR[j];
        if (tid < 12) {
            const int r = tid >> 2, c = tid & 3;
            const float* gp = &s_G[p * 12 + r * 4];
            const float* tl = &s_Tl[j * 12];
            float v = gp[0] * tl[0 * 4 + c]
                    + gp[1] * tl[1 * 4 + c]
                    + gp[2] * tl[2 * 4 + c];
            if (c == 3) v += gp[3];
            s_G[j * 12 + tid] = v;
        }
        __syncwarp();
    }

    if (tid < J) {
        const float* g = &s_G[tid * 12];
        float jx = jr[3 * tid], jy = jr[3 * tid + 1], jz = jr[3 * tid + 2];
        float tcx = g[0] * jx + g[1] * jy + g[2] * jz;
        float tcy = g[4] * jx + g[5] * jy + g[6] * jz;
        float tcz = g[8] * jx + g[9] * jy + g[10] * jz;
        g_A[tid * 3 + 0] = make_float4(g[0], g[1], g[2],  g[3]  - tcx);
        g_A[tid * 3 + 1] = make_float4(g[4], g[5], g[6],  g[7]  - tcy);
        g_A[tid * 3 + 2] = make_float4(g[8], g[9], g[10], g[11] - tcz);
    }

    // small outputs
    const long V3 = 3L * (long)V;
    const long base = (long)B * V3;
    if (tid < J) {
        out[base + 3 * tid + 0] = s_pose[3 * tid + 0];
        out[base + 3 * tid + 1] = s_pose[3 * tid + 1];
        out[base + 3 * tid + 2] = s_pose[3 * tid + 2];
    }
    __syncwarp();
    if (tid == 31) {
        float cc = cst;
        for (int j = 0; j < J; j++) {
            out[base + 69 + 3 * j + 0] = fmaf(cc, s_G[j * 12 + 3],  ox);
            out[base + 69 + 3 * j + 1] = fmaf(cc, s_G[j * 12 + 7],  oy);
            out[base + 69 + 3 * j + 2] = fmaf(cc, s_G[j * 12 + 11], oz);
        }
        out[base + 138] = scale[0];
        out[base + 139] = disp[0];
        out[base + 140] = disp[1];
        out[base + 141] = disp[2];
    }
}

// ---------------- LBS: memory-optimized, no FK ----------------
__global__ void __launch_bounds__(TPB) lbs_kernel(
    const float* __restrict__ vt,
    const float* __restrict__ sk,
    const float* __restrict__ la,
    float* __restrict__ out, int V, int B)
{
    __shared__ float  s_sk[VPB * 23];
    __shared__ float  s_vt[VPB * 3];   // reused for results after compute
    __shared__ float  s_la[VPB * 3];
    __shared__ float4 s_A4[J * 3];
    __shared__ float  s_c[4];

    const int tid = threadIdx.x;
    const long v0 = (long)blockIdx.x * VPB;
    const int nv  = (V - (int)v0 < VPB) ? (V - (int)v0) : VPB;
    const long V3 = 3L * (long)V;

    // A matrices + constants (tiny, L2-hit)
    if (tid < J * 3) s_A4[tid] = g_A[tid];
    if (tid >= 96 && tid < 100) s_c[tid - 96] = g_const[tid - 96];

    // Cooperative vectorized tile loads (streaming hint: read once)
    {
        const float4* g4 = (const float4*)(sk + v0 * 23);
        const int nS = (nv * 23) >> 2;
        #pragma unroll 3
        for (int i = tid; i < nS; i += TPB) ((float4*)s_sk)[i] = __ldcs(g4 + i);

        const float4* gv = (const float4*)(vt + v0 * 3);
        const float4* gl = (const float4*)(la + v0 * 3);
        const int n3 = (nv * 3) >> 2;
        for (int i = tid; i < n3; i += TPB) {
            ((float4*)s_vt)[i] = __ldcs(gv + i);
            ((float4*)s_la)[i] = __ldcs(gl + i);
        }
    }
    __syncthreads();

    float rx = 0.f, ry = 0.f, rz = 0.f;
    float la0 = 0.f, la1 = 0.f, la2 = 0.f;
    if (tid < nv) {
        la0 = s_la[3 * tid + 0]; la1 = s_la[3 * tid + 1]; la2 = s_la[3 * tid + 2];
        float vx = s_vt[3 * tid + 0] + 0.1f * tanhf(la0);
        float vy = s_vt[3 * tid + 1] + 0.1f * tanhf(la1);
        float vz = s_vt[3 * tid + 2] + 0.1f * tanhf(la2);

        float4 t0 = make_float4(0.f, 0.f, 0.f, 0.f);
        float4 t1 = make_float4(0.f, 0.f, 0.f, 0.f);
        float4 t2 = make_float4(0.f, 0.f, 0.f, 0.f);

        const float* skv = &s_sk[tid * 23];
        #pragma unroll
        for (int j = 0; j < J; j++) {
            float w = skv[j];
            float4 a0 = s_A4[3 * j + 0];
            float4 a1 = s_A4[3 * j + 1];
            float4 a2 = s_A4[3 * j + 2];
            t0.x = fmaf(w, a0.x, t0.x); t0.y = fmaf(w, a0.y, t0.y);
            t0.z = fmaf(w, a0.z, t0.z); t0.w = fmaf(w, a0.w, t0.w);
            t1.x = fmaf(w, a1.x, t1.x); t1.y = fmaf(w, a1.y, t1.y);
            t1.z = fmaf(w, a1.z, t1.z); t1.w = fmaf(w, a1.w, t1.w);
            t2.x = fmaf(w, a2.x, t2.x); t2.y = fmaf(w, a2.y, t2.y);
            t2.z = fmaf(w, a2.z, t2.z); t2.w = fmaf(w, a2.w, t2.w);
        }

        float x = fmaf(t0.x, vx, fmaf(t0.y, vy, fmaf(t0.z, vz, t0.w)));
        float y = fmaf(t1.x, vx, fmaf(t1.y, vy, fmaf(t1.z, vz, t1.w)));
        float z = fmaf(t2.x, vx, fmaf(t2.y, vy, fmaf(t2.z, vz, t2.w)));

        float c = s_c[0];
        rx = fmaf(c, x, s_c[1]);
        ry = fmaf(c, y, s_c[2]);
        rz = fmaf(c, z, s_c[3]);
    }
    __syncthreads();           // s_vt reads done everywhere
    if (tid < nv) {            // write results in place of s_vt
        s_vt[3 * tid + 0] = rx;
        s_vt[3 * tid + 1] = ry;
        s_vt[3 * tid + 2] = rz;
    }
    __syncthreads();

    // Cooperative vectorized streaming stores
    {
        const int n3 = (nv * 3) >> 2;
        const float4* r4 = (const float4*)s_vt;
        for (int b = 0; b < B; b++) {
            float4* go = (float4*)(out + (long)b * V3 + v0 * 3);
            for (int i = tid; i < n3; i += TPB) __stcs(go + i, r4[i]);
        }
        const long offLa = (long)B * V3 + 142;
        float2* gl2 = (float2*)(out + offLa + v0 * 3);
        const float2* l2 = (const float2*)s_la;
        const int n2 = (nv * 3) >> 1;
        for (int i = tid; i < n2; i += TPB) __stcs(gl2 + i, l2[i]);
    }
}

extern "C" void kernel_launch(void* const* d_in, const int* in_sizes, int n_in,
                              void* d_out, int out_size)
{
    const float* vt    = (const float*)d_in[0];
    const float* sk    = (const float*)d_in[1];
    const float* jr    = (const float*)d_in[2];
    const float* p0    = (const float*)d_in[3];
    const float* p1    = (const float*)d_in[4];
    const float* p2    = (const float*)d_in[5];
    const float* p3    = (const float*)d_in[6];
    const float* p4    = (const float*)d_in[7];
    const float* p5    = (const float*)d_in[8];
    const float* p12   = (const float*)d_in[9];
    const float* p13   = (const float*)d_in[10];
    const float* la    = (const float*)d_in[11];
    const float* disp  = (const float*)d_in[12];
    const float* scale = (const float*)d_in[13];
    const float* loc   = (const float*)d_in[14];
    float* out = (float*)d_out;

    int V = in_sizes[0] / 3;
    long fixed = 69L + 69L + 1L + 3L + 3L * (long)V;
    int B = (int)(((long)out_size - fixed) / (3L * (long)V));

    prep_kernel<<<1, 32>>>(jr, p0, p1, p2, p3, p4, p5, p12, p13,
                           disp, scale, loc, out, B, V);

    int blocks = (V + VPB - 1) / VPB;
    lbs_kernel<<<blocks, TPB>>>(vt, sk, la, out, V, B);
}